// round 3
// baseline (speedup 1.0000x reference)
#include <cuda_runtime.h>

#define N_NODES 20000
#define N_EDGES 640000
#define C_IN    128
#define K_FOLDS 8
#define FILTERS 128
#define ZCOLS   (K_FOLDS * FILTERS)   // 1024

// Scratch: Z[n][k][f] = (x[n] @ W_k)[f], fp32. 20000*1024*4 = 81.92 MB.
__device__ float g_Z[(size_t)N_NODES * ZCOLS];

// ---------------------------------------------------------------------------
// GEMM: Z[:, k*128:(k+1)*128] = X (20000x128) @ kernel[k] (128x128)
// Block = (64 rows) x (one fold k = 128 cols). 256 threads, 4x8 register tile.
// ---------------------------------------------------------------------------
#define BM 64
#define BK 16

__global__ __launch_bounds__(256) void gemm_zk(const float* __restrict__ X,
                                               const float* __restrict__ Wall) {
    const int mb = blockIdx.x;
    const int k  = blockIdx.y;
    const float* __restrict__ W = Wall + (size_t)k * C_IN * FILTERS;

    __shared__ float XsT[BK][BM];        // transposed X tile: [kk][row]
    __shared__ float Ws[BK][FILTERS];    // [kk][f]

    const int tid = threadIdx.x;
    const int tx  = tid & 15;            // col group: 8 cols each
    const int ty  = tid >> 4;            // row group: 4 rows each

    float acc[4][8];
#pragma unroll
    for (int i = 0; i < 4; i++)
#pragma unroll
        for (int j = 0; j < 8; j++) acc[i][j] = 0.0f;

    const int xr  = tid >> 2;            // 0..63 row within tile
    const int xc4 = tid & 3;             // 0..3  float4 within 16-wide K chunk
    const int grow = mb * BM + xr;

#pragma unroll
    for (int kb = 0; kb < C_IN / BK; ++kb) {
        __syncthreads();
        // load X tile (64x16) transposed
        float4 xv = make_float4(0.f, 0.f, 0.f, 0.f);
        if (grow < N_NODES)
            xv = *reinterpret_cast<const float4*>(X + (size_t)grow * C_IN + kb * BK + xc4 * 4);
        XsT[xc4 * 4 + 0][xr] = xv.x;
        XsT[xc4 * 4 + 1][xr] = xv.y;
        XsT[xc4 * 4 + 2][xr] = xv.z;
        XsT[xc4 * 4 + 3][xr] = xv.w;
        // load W tile (16x128)
#pragma unroll
        for (int p = tid; p < BK * FILTERS / 4; p += 256) {
            int kk = p >> 5;
            int f4 = p & 31;
            *reinterpret_cast<float4*>(&Ws[kk][f4 * 4]) =
                *reinterpret_cast<const float4*>(W + (size_t)(kb * BK + kk) * FILTERS + f4 * 4);
        }
        __syncthreads();

#pragma unroll
        for (int kk = 0; kk < BK; ++kk) {
            const float4 av  = *reinterpret_cast<const float4*>(&XsT[kk][ty * 4]);
            const float4 bv0 = *reinterpret_cast<const float4*>(&Ws[kk][tx * 8]);
            const float4 bv1 = *reinterpret_cast<const float4*>(&Ws[kk][tx * 8 + 4]);
            const float a[4] = {av.x, av.y, av.z, av.w};
            const float b[8] = {bv0.x, bv0.y, bv0.z, bv0.w, bv1.x, bv1.y, bv1.z, bv1.w};
#pragma unroll
            for (int i = 0; i < 4; i++)
#pragma unroll
                for (int j = 0; j < 8; j++) acc[i][j] += a[i] * b[j];
        }
    }

#pragma unroll
    for (int i = 0; i < 4; i++) {
        const int row = mb * BM + ty * 4 + i;
        if (row < N_NODES) {
            float* zp = g_Z + (size_t)row * ZCOLS + k * FILTERS + tx * 8;
            *reinterpret_cast<float4*>(zp)     = make_float4(acc[i][0], acc[i][1], acc[i][2], acc[i][3]);
            *reinterpret_cast<float4*>(zp + 4) = make_float4(acc[i][4], acc[i][5], acc[i][6], acc[i][7]);
        }
    }
}

// ---------------------------------------------------------------------------
// out init: out[n][f] = bias[f]
// ---------------------------------------------------------------------------
__global__ __launch_bounds__(256) void init_out(float* __restrict__ out,
                                                const float* __restrict__ bias) {
    const int i = blockIdx.x * 256 + threadIdx.x;
    out[i] = bias[i & (FILTERS - 1)];
}

// ---------------------------------------------------------------------------
// Edge pass: one warp per edge. indices are int32 (JAX x64 is disabled, so
// .astype(int64) was a no-op): layout (E,2) -> row=idx[2e], col=idx[2e+1].
//   acc[lane*4 .. +3] = sum_k ef[k,e] * Z[col_e][k][lane*4 .. +3]
//   red.global.add.v4.f32 into out[row_e]
// ---------------------------------------------------------------------------
__global__ __launch_bounds__(256) void edge_scatter(const float* __restrict__ ef,
                                                    const int* __restrict__ idx,
                                                    float* __restrict__ out) {
    const int e    = blockIdx.x * 8 + (threadIdx.x >> 5);
    const int lane = threadIdx.x & 31;

    const int2 rc = reinterpret_cast<const int2*>(idx)[e];
    const int row = rc.x;
    const int col = rc.y;

    float w[K_FOLDS];
#pragma unroll
    for (int k = 0; k < K_FOLDS; k++) w[k] = ef[(size_t)k * N_EDGES + e];

    const float4* zc = reinterpret_cast<const float4*>(g_Z + (size_t)col * ZCOLS) + lane;
    float4 acc = make_float4(0.f, 0.f, 0.f, 0.f);
#pragma unroll
    for (int k = 0; k < K_FOLDS; k++) {
        const float4 z = zc[k * 32];
        acc.x += w[k] * z.x;
        acc.y += w[k] * z.y;
        acc.z += w[k] * z.z;
        acc.w += w[k] * z.w;
    }

    float* dst = out + (size_t)row * FILTERS + lane * 4;
    asm volatile("red.global.add.v4.f32 [%0], {%1, %2, %3, %4};"
                 :: "l"(dst), "f"(acc.x), "f"(acc.y), "f"(acc.z), "f"(acc.w)
                 : "memory");
}

// ---------------------------------------------------------------------------
extern "C" void kernel_launch(void* const* d_in, const int* in_sizes, int n_in,
                              void* d_out, int out_size) {
    const float* X    = (const float*)d_in[0];   // node_features (20000,128)
    const float* ef   = (const float*)d_in[1];   // edge_features (8,640000)
    const float* Wall = (const float*)d_in[2];   // kernel (8,128,128)
    const float* bias = (const float*)d_in[3];   // bias (128,)
    const int*   idx  = (const int*)d_in[4];     // indices (640000,2) int32
    float*       out  = (float*)d_out;           // (20000,128)

    dim3 ggrid((N_NODES + BM - 1) / BM, K_FOLDS);
    gemm_zk<<<ggrid, 256>>>(X, Wall);

    init_out<<<(N_NODES * FILTERS) / 256, 256>>>(out, bias);

    edge_scatter<<<N_EDGES / 8, 256>>>(ef, idx, out);
}

// round 4
// speedup vs baseline: 1.3536x; 1.3536x over previous
#include <cuda_runtime.h>

#define N_NODES 20000
#define N_EDGES 640000
#define C_IN    128
#define K_FOLDS 8
#define FILTERS 128
#define ZCOLS   (K_FOLDS * FILTERS)   // 1024

typedef unsigned long long ull;

// Scratch: Z[n][k][f] = (x[n] @ W_k)[f], fp32. 20000*1024*4 = 81.92 MB.
__device__ float g_Z[(size_t)N_NODES * ZCOLS];

#define PACK2(d, x, y)   asm("mov.b64 %0, {%1,%2};" : "=l"(d) : "f"(x), "f"(y))
#define UNPACK2(x, y, d) asm("mov.b64 {%0,%1}, %2;" : "=f"(x), "=f"(y) : "l"(d))
#define FFMA2(acc, a, b) asm("fma.rn.f32x2 %0, %1, %2, %0;" : "+l"(acc) : "l"(a), "l"(b))

// ---------------------------------------------------------------------------
// GEMM: Z[:, k*128:(k+1)*128] = X (20000x128) @ kernel[k] (128x128)
// 128x128 block tile, 256 threads, 8x8/thread (split 4+4), BK=8,
// double-buffered smem, packed f32x2 FFMA inner loop.
// ---------------------------------------------------------------------------
#define GBM 128
#define GBK 8
#define NSTAGE (C_IN / GBK)   // 16

__global__ __launch_bounds__(256, 2) void gemm_zk(const float* __restrict__ X,
                                                  const float* __restrict__ Wall) {
    const int mb = blockIdx.x;
    const int k  = blockIdx.y;
    const float* __restrict__ W = Wall + (size_t)k * C_IN * FILTERS;

    __shared__ float Xs[2][GBK][GBM];      // [kk][row]
    __shared__ float Ws[2][GBK][FILTERS];  // [kk][f]

    const int tid = threadIdx.x;
    const int tx  = tid & 15;              // col fragment: tx*4 and 64+tx*4
    const int ty  = tid >> 4;              // row fragment: ty*4 and 64+ty*4

    // global load mapping
    const int lrow  = tid >> 1;            // 0..127
    const int lhalf = (tid & 1) * 4;       // 0 or 4 within GBK
    const int crow  = min(mb * GBM + lrow, N_NODES - 1);
    const int wr    = tid >> 5;            // 0..7 (kk)
    const int wf    = (tid & 31) * 4;      // 0..124

    ull acc[8][4];
#pragma unroll
    for (int i = 0; i < 8; i++)
#pragma unroll
        for (int j = 0; j < 4; j++) acc[i][j] = 0ull;

    // prime stage 0
    float4 xv = *reinterpret_cast<const float4*>(X + (size_t)crow * C_IN + lhalf);
    float4 wv = *reinterpret_cast<const float4*>(W + (size_t)wr * FILTERS + wf);
    Xs[0][lhalf + 0][lrow] = xv.x;
    Xs[0][lhalf + 1][lrow] = xv.y;
    Xs[0][lhalf + 2][lrow] = xv.z;
    Xs[0][lhalf + 3][lrow] = xv.w;
    *reinterpret_cast<float4*>(&Ws[0][wr][wf]) = wv;
    __syncthreads();

#pragma unroll
    for (int kb = 0; kb < NSTAGE; ++kb) {
        const int buf = kb & 1;
        float4 xn, wn;
        if (kb < NSTAGE - 1) {
            const int c0 = (kb + 1) * GBK;
            xn = *reinterpret_cast<const float4*>(X + (size_t)crow * C_IN + c0 + lhalf);
            wn = *reinterpret_cast<const float4*>(W + (size_t)(c0 + wr) * FILTERS + wf);
        }

#pragma unroll
        for (int kk = 0; kk < GBK; ++kk) {
            const float4 av0 = *reinterpret_cast<const float4*>(&Xs[buf][kk][ty * 4]);
            const float4 av1 = *reinterpret_cast<const float4*>(&Xs[buf][kk][64 + ty * 4]);
            const float4 bv0 = *reinterpret_cast<const float4*>(&Ws[buf][kk][tx * 4]);
            const float4 bv1 = *reinterpret_cast<const float4*>(&Ws[buf][kk][64 + tx * 4]);
            ull b[4];
            PACK2(b[0], bv0.x, bv0.y);
            PACK2(b[1], bv0.z, bv0.w);
            PACK2(b[2], bv1.x, bv1.y);
            PACK2(b[3], bv1.z, bv1.w);
            const float a[8] = {av0.x, av0.y, av0.z, av0.w, av1.x, av1.y, av1.z, av1.w};
#pragma unroll
            for (int i = 0; i < 8; i++) {
                ull ap;
                PACK2(ap, a[i], a[i]);
                FFMA2(acc[i][0], ap, b[0]);
                FFMA2(acc[i][1], ap, b[1]);
                FFMA2(acc[i][2], ap, b[2]);
                FFMA2(acc[i][3], ap, b[3]);
            }
        }

        if (kb < NSTAGE - 1) {
            const int nbuf = buf ^ 1;
            Xs[nbuf][lhalf + 0][lrow] = xn.x;
            Xs[nbuf][lhalf + 1][lrow] = xn.y;
            Xs[nbuf][lhalf + 2][lrow] = xn.z;
            Xs[nbuf][lhalf + 3][lrow] = xn.w;
            *reinterpret_cast<float4*>(&Ws[nbuf][wr][wf]) = wn;
            __syncthreads();
        }
    }

    // epilogue
#pragma unroll
    for (int i = 0; i < 8; i++) {
        const int rloc = (i < 4) ? (ty * 4 + i) : (64 + ty * 4 + (i - 4));
        const int row  = mb * GBM + rloc;
        if (row < N_NODES) {
            float o[8];
            UNPACK2(o[0], o[1], acc[i][0]);
            UNPACK2(o[2], o[3], acc[i][1]);
            UNPACK2(o[4], o[5], acc[i][2]);
            UNPACK2(o[6], o[7], acc[i][3]);
            float* zp = g_Z + (size_t)row * ZCOLS + k * FILTERS;
            *reinterpret_cast<float4*>(zp + tx * 4)      = make_float4(o[0], o[1], o[2], o[3]);
            *reinterpret_cast<float4*>(zp + 64 + tx * 4) = make_float4(o[4], o[5], o[6], o[7]);
        }
    }
}

// ---------------------------------------------------------------------------
// out init: out[n][f] = bias[f]
// ---------------------------------------------------------------------------
__global__ __launch_bounds__(256) void init_out(float* __restrict__ out,
                                                const float* __restrict__ bias) {
    const int i = blockIdx.x * 256 + threadIdx.x;
    out[i] = bias[i & (FILTERS - 1)];
}

// ---------------------------------------------------------------------------
// Edge pass: one warp per edge. indices are int32: row=idx[2e], col=idx[2e+1].
//   acc[lane*4 .. +3] = sum_k ef[k,e] * Z[col_e][k][lane*4 .. +3]
//   red.global.add.v4.f32 into out[row_e]
// ---------------------------------------------------------------------------
__global__ __launch_bounds__(256) void edge_scatter(const float* __restrict__ ef,
                                                    const int* __restrict__ idx,
                                                    float* __restrict__ out) {
    const int e    = blockIdx.x * 8 + (threadIdx.x >> 5);
    const int lane = threadIdx.x & 31;

    const int2 rc = reinterpret_cast<const int2*>(idx)[e];
    const int row = rc.x;
    const int col = rc.y;

    float w[K_FOLDS];
#pragma unroll
    for (int k = 0; k < K_FOLDS; k++) w[k] = ef[(size_t)k * N_EDGES + e];

    const float4* zc = reinterpret_cast<const float4*>(g_Z + (size_t)col * ZCOLS) + lane;
    float4 acc = make_float4(0.f, 0.f, 0.f, 0.f);
#pragma unroll
    for (int k = 0; k < K_FOLDS; k++) {
        const float4 z = zc[k * 32];
        acc.x += w[k] * z.x;
        acc.y += w[k] * z.y;
        acc.z += w[k] * z.z;
        acc.w += w[k] * z.w;
    }

    float* dst = out + (size_t)row * FILTERS + lane * 4;
    asm volatile("red.global.add.v4.f32 [%0], {%1, %2, %3, %4};"
                 :: "l"(dst), "f"(acc.x), "f"(acc.y), "f"(acc.z), "f"(acc.w)
                 : "memory");
}

// ---------------------------------------------------------------------------
extern "C" void kernel_launch(void* const* d_in, const int* in_sizes, int n_in,
                              void* d_out, int out_size) {
    const float* X    = (const float*)d_in[0];   // node_features (20000,128)
    const float* ef   = (const float*)d_in[1];   // edge_features (8,640000)
    const float* Wall = (const float*)d_in[2];   // kernel (8,128,128)
    const float* bias = (const float*)d_in[3];   // bias (128,)
    const int*   idx  = (const int*)d_in[4];     // indices (640000,2) int32
    float*       out  = (float*)d_out;           // (20000,128)

    dim3 ggrid((N_NODES + GBM - 1) / GBM, K_FOLDS);
    gemm_zk<<<ggrid, 256>>>(X, Wall);

    init_out<<<(N_NODES * FILTERS) / 256, 256>>>(out, bias);

    edge_scatter<<<N_EDGES / 8, 256>>>(ef, idx, out);
}

// round 5
// speedup vs baseline: 1.4918x; 1.1021x over previous
#include <cuda_runtime.h>

#define N_NODES 20000
#define N_EDGES 640000
#define C_IN    128
#define K_FOLDS 8
#define FILTERS 128
#define ZCOLS   (K_FOLDS * FILTERS)   // 1024

typedef unsigned long long ull;

// Scratch
__device__ float g_Z[(size_t)N_NODES * ZCOLS];     // 81.92 MB
__device__ int   g_hist[N_NODES];                  // per-col counts
__device__ int   g_start[N_NODES + 1];             // exclusive scan (preserved)
__device__ int   g_cur[N_NODES];                   // running cursor for scatter
__device__ int   g_srow[N_EDGES];                  // rows in col-sorted order
__device__ float g_w8[(size_t)N_EDGES * K_FOLDS];  // per-edge weights, sorted, 20.5 MB

#define PACK2(d, x, y)   asm("mov.b64 %0, {%1,%2};" : "=l"(d) : "f"(x), "f"(y))
#define UNPACK2(x, y, d) asm("mov.b64 {%0,%1}, %2;" : "=f"(x), "=f"(y) : "l"(d))
#define FFMA2(acc, a, b) asm("fma.rn.f32x2 %0, %1, %2, %0;" : "+l"(acc) : "l"(a), "l"(b))

// ---------------------------------------------------------------------------
// GEMM: Z[:, k*128:(k+1)*128] = X (20000x128) @ kernel[k] (128x128)
// 128x128 block tile, 256 threads, 8x8/thread, BK=8, double-buffered, FFMA2.
// ---------------------------------------------------------------------------
#define GBM 128
#define GBK 8
#define NSTAGE (C_IN / GBK)   // 16

__global__ __launch_bounds__(256, 2) void gemm_zk(const float* __restrict__ X,
                                                  const float* __restrict__ Wall) {
    const int mb = blockIdx.x;
    const int k  = blockIdx.y;
    const float* __restrict__ W = Wall + (size_t)k * C_IN * FILTERS;

    __shared__ float Xs[2][GBK][GBM];
    __shared__ float Ws[2][GBK][FILTERS];

    const int tid = threadIdx.x;
    const int tx  = tid & 15;
    const int ty  = tid >> 4;

    const int lrow  = tid >> 1;
    const int lhalf = (tid & 1) * 4;
    const int crow  = min(mb * GBM + lrow, N_NODES - 1);
    const int wr    = tid >> 5;
    const int wf    = (tid & 31) * 4;

    ull acc[8][4];
#pragma unroll
    for (int i = 0; i < 8; i++)
#pragma unroll
        for (int j = 0; j < 4; j++) acc[i][j] = 0ull;

    float4 xv = *reinterpret_cast<const float4*>(X + (size_t)crow * C_IN + lhalf);
    float4 wv = *reinterpret_cast<const float4*>(W + (size_t)wr * FILTERS + wf);
    Xs[0][lhalf + 0][lrow] = xv.x;
    Xs[0][lhalf + 1][lrow] = xv.y;
    Xs[0][lhalf + 2][lrow] = xv.z;
    Xs[0][lhalf + 3][lrow] = xv.w;
    *reinterpret_cast<float4*>(&Ws[0][wr][wf]) = wv;
    __syncthreads();

#pragma unroll
    for (int kb = 0; kb < NSTAGE; ++kb) {
        const int buf = kb & 1;
        float4 xn, wn;
        if (kb < NSTAGE - 1) {
            const int c0 = (kb + 1) * GBK;
            xn = *reinterpret_cast<const float4*>(X + (size_t)crow * C_IN + c0 + lhalf);
            wn = *reinterpret_cast<const float4*>(W + (size_t)(c0 + wr) * FILTERS + wf);
        }

#pragma unroll
        for (int kk = 0; kk < GBK; ++kk) {
            const float4 av0 = *reinterpret_cast<const float4*>(&Xs[buf][kk][ty * 4]);
            const float4 av1 = *reinterpret_cast<const float4*>(&Xs[buf][kk][64 + ty * 4]);
            const float4 bv0 = *reinterpret_cast<const float4*>(&Ws[buf][kk][tx * 4]);
            const float4 bv1 = *reinterpret_cast<const float4*>(&Ws[buf][kk][64 + tx * 4]);
            ull b[4];
            PACK2(b[0], bv0.x, bv0.y);
            PACK2(b[1], bv0.z, bv0.w);
            PACK2(b[2], bv1.x, bv1.y);
            PACK2(b[3], bv1.z, bv1.w);
            const float a[8] = {av0.x, av0.y, av0.z, av0.w, av1.x, av1.y, av1.z, av1.w};
#pragma unroll
            for (int i = 0; i < 8; i++) {
                ull ap;
                PACK2(ap, a[i], a[i]);
                FFMA2(acc[i][0], ap, b[0]);
                FFMA2(acc[i][1], ap, b[1]);
                FFMA2(acc[i][2], ap, b[2]);
                FFMA2(acc[i][3], ap, b[3]);
            }
        }

        if (kb < NSTAGE - 1) {
            const int nbuf = buf ^ 1;
            Xs[nbuf][lhalf + 0][lrow] = xn.x;
            Xs[nbuf][lhalf + 1][lrow] = xn.y;
            Xs[nbuf][lhalf + 2][lrow] = xn.z;
            Xs[nbuf][lhalf + 3][lrow] = xn.w;
            *reinterpret_cast<float4*>(&Ws[nbuf][wr][wf]) = wn;
            __syncthreads();
        }
    }

#pragma unroll
    for (int i = 0; i < 8; i++) {
        const int rloc = (i < 4) ? (ty * 4 + i) : (64 + ty * 4 + (i - 4));
        const int row  = mb * GBM + rloc;
        if (row < N_NODES) {
            float o[8];
            UNPACK2(o[0], o[1], acc[i][0]);
            UNPACK2(o[2], o[3], acc[i][1]);
            UNPACK2(o[4], o[5], acc[i][2]);
            UNPACK2(o[6], o[7], acc[i][3]);
            float* zp = g_Z + (size_t)row * ZCOLS + k * FILTERS;
            *reinterpret_cast<float4*>(zp + tx * 4)      = make_float4(o[0], o[1], o[2], o[3]);
            *reinterpret_cast<float4*>(zp + 64 + tx * 4) = make_float4(o[4], o[5], o[6], o[7]);
        }
    }
}

// ---------------------------------------------------------------------------
// Counting sort by col
// ---------------------------------------------------------------------------
__global__ __launch_bounds__(256) void zero_hist() {
    const int i = blockIdx.x * 256 + threadIdx.x;
    if (i < N_NODES) g_hist[i] = 0;
}

__global__ __launch_bounds__(256) void hist_cols(const int* __restrict__ idx) {
    const int e = blockIdx.x * 256 + threadIdx.x;
    const int col = reinterpret_cast<const int2*>(idx)[e].y;
    atomicAdd(&g_hist[col], 1);
}

__global__ __launch_bounds__(1024) void scan_hist() {
    __shared__ int s[1024];
    __shared__ int chunk_total;
    const int tid = threadIdx.x;
    int run = 0;
    const int nchunks = (N_NODES + 1023) / 1024;
    for (int c = 0; c < nchunks; ++c) {
        const int i = c * 1024 + tid;
        const int v = (i < N_NODES) ? g_hist[i] : 0;
        s[tid] = v;
        __syncthreads();
#pragma unroll
        for (int off = 1; off < 1024; off <<= 1) {
            int t = (tid >= off) ? s[tid - off] : 0;
            __syncthreads();
            s[tid] += t;
            __syncthreads();
        }
        const int excl = s[tid] - v;
        if (i < N_NODES) {
            g_start[i] = run + excl;
            g_cur[i]   = run + excl;
        }
        if (tid == 1023) chunk_total = s[1023];
        __syncthreads();
        run += chunk_total;
        __syncthreads();
    }
    if (tid == 0) g_start[N_NODES] = run;   // == N_EDGES
}

// Scatter edges into col-sorted order; pre-gather the 8 weights per edge.
__global__ __launch_bounds__(256) void scatter_sort(const int* __restrict__ idx,
                                                    const float* __restrict__ ef) {
    const int e = blockIdx.x * 256 + threadIdx.x;
    const int2 rc = reinterpret_cast<const int2*>(idx)[e];
    const int pos = atomicAdd(&g_cur[rc.y], 1);
    g_srow[pos] = rc.x;
    float w[K_FOLDS];
#pragma unroll
    for (int k = 0; k < K_FOLDS; k++) w[k] = ef[(size_t)k * N_EDGES + e];
    float4* wp = reinterpret_cast<float4*>(g_w8 + (size_t)pos * K_FOLDS);
    wp[0] = make_float4(w[0], w[1], w[2], w[3]);
    wp[1] = make_float4(w[4], w[5], w[6], w[7]);
}

// ---------------------------------------------------------------------------
// out init: out[n][f] = bias[f]
// ---------------------------------------------------------------------------
__global__ __launch_bounds__(256) void init_out(float* __restrict__ out,
                                                const float* __restrict__ bias) {
    const int i = blockIdx.x * 256 + threadIdx.x;
    out[i] = bias[i & (FILTERS - 1)];
}

// ---------------------------------------------------------------------------
// Edge pass: one warp per COL. Z[c] is loaded once into registers
// (32 floats/lane), then each edge in the segment does 32 FMA/lane and one
// red.global.add.v4 into out[row].
// ---------------------------------------------------------------------------
__global__ __launch_bounds__(256) void col_scatter(float* __restrict__ out) {
    const int c    = blockIdx.x * 8 + (threadIdx.x >> 5);
    const int lane = threadIdx.x & 31;
    if (c >= N_NODES) return;

    const int beg = g_start[c];
    const int end = g_start[c + 1];
    if (beg == end) return;

    // Z[c][k][lane*4 .. +3] for all k
    const float4* zp = reinterpret_cast<const float4*>(g_Z + (size_t)c * ZCOLS) + lane;
    float4 z[K_FOLDS];
#pragma unroll
    for (int k = 0; k < K_FOLDS; k++) z[k] = zp[k * 32];

    for (int e = beg; e < end; ++e) {
        const int row = g_srow[e];                       // broadcast
        const float4* wp = reinterpret_cast<const float4*>(g_w8 + (size_t)e * K_FOLDS);
        const float4 w0 = wp[0];                         // broadcast
        const float4 w1 = wp[1];
        const float w[K_FOLDS] = {w0.x, w0.y, w0.z, w0.w, w1.x, w1.y, w1.z, w1.w};

        float4 acc = make_float4(0.f, 0.f, 0.f, 0.f);
#pragma unroll
        for (int k = 0; k < K_FOLDS; k++) {
            acc.x += w[k] * z[k].x;
            acc.y += w[k] * z[k].y;
            acc.z += w[k] * z[k].z;
            acc.w += w[k] * z[k].w;
        }

        float* dst = out + (size_t)row * FILTERS + lane * 4;
        asm volatile("red.global.add.v4.f32 [%0], {%1, %2, %3, %4};"
                     :: "l"(dst), "f"(acc.x), "f"(acc.y), "f"(acc.z), "f"(acc.w)
                     : "memory");
    }
}

// ---------------------------------------------------------------------------
extern "C" void kernel_launch(void* const* d_in, const int* in_sizes, int n_in,
                              void* d_out, int out_size) {
    const float* X    = (const float*)d_in[0];   // node_features (20000,128)
    const float* ef   = (const float*)d_in[1];   // edge_features (8,640000)
    const float* Wall = (const float*)d_in[2];   // kernel (8,128,128)
    const float* bias = (const float*)d_in[3];   // bias (128,)
    const int*   idx  = (const int*)d_in[4];     // indices (640000,2) int32
    float*       out  = (float*)d_out;           // (20000,128)

    dim3 ggrid((N_NODES + GBM - 1) / GBM, K_FOLDS);
    gemm_zk<<<ggrid, 256>>>(X, Wall);

    zero_hist<<<(N_NODES + 255) / 256, 256>>>();
    hist_cols<<<N_EDGES / 256, 256>>>(idx);
    scan_hist<<<1, 1024>>>();
    scatter_sort<<<N_EDGES / 256, 256>>>(idx, ef);

    init_out<<<(N_NODES * FILTERS) / 256, 256>>>(out, bias);

    col_scatter<<<(N_NODES + 7) / 8, 256>>>(out);
}

// round 6
// speedup vs baseline: 1.5820x; 1.0604x over previous
#include <cuda_runtime.h>

#define N_NODES 20000
#define N_EDGES 640000
#define C_IN    128
#define K_FOLDS 8
#define FILTERS 128
#define ZCOLS   (K_FOLDS * C_IN)   // 1024

typedef unsigned long long ull;

// Scratch
__device__ float g_Y[(size_t)N_NODES * ZCOLS];     // Y[r][k][c], 81.92 MB
__device__ int   g_hist[N_NODES];
__device__ int   g_start[N_NODES + 1];
__device__ int   g_cur[N_NODES];
__device__ int   g_scol[N_EDGES];                  // cols in row-sorted order
__device__ float g_w8[(size_t)N_EDGES * K_FOLDS];  // weights in row-sorted order

#define PACK2(d, x, y)   asm("mov.b64 %0, {%1,%2};" : "=l"(d) : "f"(x), "f"(y))
#define UNPACK2(x, y, d) asm("mov.b64 {%0,%1}, %2;" : "=f"(x), "=f"(y) : "l"(d))
#define FFMA2(acc, a, b) asm("fma.rn.f32x2 %0, %1, %2, %0;" : "+l"(acc) : "l"(a), "l"(b))

// ---------------------------------------------------------------------------
// Counting sort by ROW
// ---------------------------------------------------------------------------
__global__ __launch_bounds__(256) void zero_hist() {
    const int i = blockIdx.x * 256 + threadIdx.x;
    if (i < N_NODES) g_hist[i] = 0;
}

__global__ __launch_bounds__(256) void hist_rows(const int* __restrict__ idx) {
    const int e = blockIdx.x * 256 + threadIdx.x;
    const int row = reinterpret_cast<const int2*>(idx)[e].x;
    atomicAdd(&g_hist[row], 1);
}

#define BINS_PER_THREAD 20   // 1024*20 >= 20000
__global__ __launch_bounds__(1024) void scan_hist() {
    const int tid  = threadIdx.x;
    const int lane = tid & 31;
    const int wid  = tid >> 5;
    const int base = tid * BINS_PER_THREAD;

    int local[BINS_PER_THREAD];
    int sum = 0;
#pragma unroll
    for (int i = 0; i < BINS_PER_THREAD; i++) {
        const int b = base + i;
        const int v = (b < N_NODES) ? g_hist[b] : 0;
        local[i] = v;
        sum += v;
    }
    // warp inclusive scan
    int x = sum;
#pragma unroll
    for (int off = 1; off < 32; off <<= 1) {
        int t = __shfl_up_sync(0xffffffffu, x, off);
        if (lane >= off) x += t;
    }
    __shared__ int wsum[32];
    if (lane == 31) wsum[wid] = x;
    __syncthreads();
    if (wid == 0) {
        int w = wsum[lane];
#pragma unroll
        for (int off = 1; off < 32; off <<= 1) {
            int t = __shfl_up_sync(0xffffffffu, w, off);
            if (lane >= off) w += t;
        }
        wsum[lane] = w;
    }
    __syncthreads();
    int run = x - sum + (wid > 0 ? wsum[wid - 1] : 0);
#pragma unroll
    for (int i = 0; i < BINS_PER_THREAD; i++) {
        const int b = base + i;
        if (b < N_NODES) {
            g_start[b] = run;
            g_cur[b]   = run;
            run += local[i];
        }
    }
    if (tid == 1023) g_start[N_NODES] = N_EDGES;
}

// Scatter edges into row-sorted order; pre-gather the 8 weights per edge.
__global__ __launch_bounds__(256) void scatter_sort(const int* __restrict__ idx,
                                                    const float* __restrict__ ef) {
    const int e = blockIdx.x * 256 + threadIdx.x;
    const int2 rc = reinterpret_cast<const int2*>(idx)[e];
    const int pos = atomicAdd(&g_cur[rc.x], 1);
    g_scol[pos] = rc.y;
    float w[K_FOLDS];
#pragma unroll
    for (int k = 0; k < K_FOLDS; k++) w[k] = ef[(size_t)k * N_EDGES + e];
    float4* wp = reinterpret_cast<float4*>(g_w8 + (size_t)pos * K_FOLDS);
    wp[0] = make_float4(w[0], w[1], w[2], w[3]);
    wp[1] = make_float4(w[4], w[5], w[6], w[7]);
}

// ---------------------------------------------------------------------------
// row_gather: one warp per row. Y[r][k][c] = sum_{e in row r} ef[k,e]*x[col_e][c]
// Accumulates 8 folds x 4 floats per lane in registers; zero atomics.
// ---------------------------------------------------------------------------
__global__ __launch_bounds__(256) void row_gather(const float* __restrict__ X) {
    const int r    = blockIdx.x * 8 + (threadIdx.x >> 5);
    const int lane = threadIdx.x & 31;
    if (r >= N_NODES) return;

    const int beg = g_start[r];
    const int end = g_start[r + 1];

    ull acc[K_FOLDS][2];
#pragma unroll
    for (int k = 0; k < K_FOLDS; k++) { acc[k][0] = 0ull; acc[k][1] = 0ull; }

    int e = beg;
    for (; e + 1 < end; e += 2) {
        const int c0 = g_scol[e];
        const int c1 = g_scol[e + 1];
        const float4 xv0 = reinterpret_cast<const float4*>(X + (size_t)c0 * C_IN)[lane];
        const float4 xv1 = reinterpret_cast<const float4*>(X + (size_t)c1 * C_IN)[lane];
        const float4* wp = reinterpret_cast<const float4*>(g_w8 + (size_t)e * K_FOLDS);
        const float4 wa0 = wp[0], wa1 = wp[1], wb0 = wp[2], wb1 = wp[3];
        const float wa[K_FOLDS] = {wa0.x, wa0.y, wa0.z, wa0.w, wa1.x, wa1.y, wa1.z, wa1.w};
        const float wb[K_FOLDS] = {wb0.x, wb0.y, wb0.z, wb0.w, wb1.x, wb1.y, wb1.z, wb1.w};
        ull x0lo, x0hi, x1lo, x1hi;
        PACK2(x0lo, xv0.x, xv0.y); PACK2(x0hi, xv0.z, xv0.w);
        PACK2(x1lo, xv1.x, xv1.y); PACK2(x1hi, xv1.z, xv1.w);
#pragma unroll
        for (int k = 0; k < K_FOLDS; k++) {
            ull wk0, wk1;
            PACK2(wk0, wa[k], wa[k]);
            PACK2(wk1, wb[k], wb[k]);
            FFMA2(acc[k][0], wk0, x0lo);
            FFMA2(acc[k][1], wk0, x0hi);
            FFMA2(acc[k][0], wk1, x1lo);
            FFMA2(acc[k][1], wk1, x1hi);
        }
    }
    if (e < end) {
        const int c0 = g_scol[e];
        const float4 xv0 = reinterpret_cast<const float4*>(X + (size_t)c0 * C_IN)[lane];
        const float4* wp = reinterpret_cast<const float4*>(g_w8 + (size_t)e * K_FOLDS);
        const float4 wa0 = wp[0], wa1 = wp[1];
        const float wa[K_FOLDS] = {wa0.x, wa0.y, wa0.z, wa0.w, wa1.x, wa1.y, wa1.z, wa1.w};
        ull x0lo, x0hi;
        PACK2(x0lo, xv0.x, xv0.y); PACK2(x0hi, xv0.z, xv0.w);
#pragma unroll
        for (int k = 0; k < K_FOLDS; k++) {
            ull wk0;
            PACK2(wk0, wa[k], wa[k]);
            FFMA2(acc[k][0], wk0, x0lo);
            FFMA2(acc[k][1], wk0, x0hi);
        }
    }

    float* yp = g_Y + (size_t)r * ZCOLS;
#pragma unroll
    for (int k = 0; k < K_FOLDS; k++) {
        float a, b, c, d;
        UNPACK2(a, b, acc[k][0]);
        UNPACK2(c, d, acc[k][1]);
        reinterpret_cast<float4*>(yp + k * C_IN)[lane] = make_float4(a, b, c, d);
    }
}

// ---------------------------------------------------------------------------
// out init: out[n][f] = bias[f]
// ---------------------------------------------------------------------------
__global__ __launch_bounds__(256) void init_out(float* __restrict__ out,
                                                const float* __restrict__ bias) {
    const int i = blockIdx.x * 256 + threadIdx.x;
    out[i] = bias[i & (FILTERS - 1)];
}

// ---------------------------------------------------------------------------
// GEMM + scatter epilogue: out += Y[:, k*128:(k+1)*128] @ kernel[k]
// 128x128 block tile, 256 threads, 8x8/thread, BK=8, double-buffered, FFMA2.
// Epilogue: red.global.add.v4 into out (8 folds accumulate there).
// ---------------------------------------------------------------------------
#define GBM 128
#define GBK 8
#define NSTAGE (C_IN / GBK)   // 16

__global__ __launch_bounds__(256, 2) void gemm_out(const float* __restrict__ Wall,
                                                   float* __restrict__ out) {
    const int mb = blockIdx.x;
    const int k  = blockIdx.y;
    const float* __restrict__ W = Wall + (size_t)k * C_IN * FILTERS;
    const float* __restrict__ A = g_Y + (size_t)k * C_IN;   // column block k

    __shared__ float Xs[2][GBK][GBM];
    __shared__ float Ws[2][GBK][FILTERS];

    const int tid = threadIdx.x;
    const int tx  = tid & 15;
    const int ty  = tid >> 4;

    const int lrow  = tid >> 1;
    const int lhalf = (tid & 1) * 4;
    const int crow  = min(mb * GBM + lrow, N_NODES - 1);
    const int wr    = tid >> 5;
    const int wf    = (tid & 31) * 4;

    ull acc[8][4];
#pragma unroll
    for (int i = 0; i < 8; i++)
#pragma unroll
        for (int j = 0; j < 4; j++) acc[i][j] = 0ull;

    float4 xv = *reinterpret_cast<const float4*>(A + (size_t)crow * ZCOLS + lhalf);
    float4 wv = *reinterpret_cast<const float4*>(W + (size_t)wr * FILTERS + wf);
    Xs[0][lhalf + 0][lrow] = xv.x;
    Xs[0][lhalf + 1][lrow] = xv.y;
    Xs[0][lhalf + 2][lrow] = xv.z;
    Xs[0][lhalf + 3][lrow] = xv.w;
    *reinterpret_cast<float4*>(&Ws[0][wr][wf]) = wv;
    __syncthreads();

#pragma unroll
    for (int kb = 0; kb < NSTAGE; ++kb) {
        const int buf = kb & 1;
        float4 xn, wn;
        if (kb < NSTAGE - 1) {
            const int c0 = (kb + 1) * GBK;
            xn = *reinterpret_cast<const float4*>(A + (size_t)crow * ZCOLS + c0 + lhalf);
            wn = *reinterpret_cast<const float4*>(W + (size_t)(c0 + wr) * FILTERS + wf);
        }

#pragma unroll
        for (int kk = 0; kk < GBK; ++kk) {
            const float4 av0 = *reinterpret_cast<const float4*>(&Xs[buf][kk][ty * 4]);
            const float4 av1 = *reinterpret_cast<const float4*>(&Xs[buf][kk][64 + ty * 4]);
            const float4 bv0 = *reinterpret_cast<const float4*>(&Ws[buf][kk][tx * 4]);
            const float4 bv1 = *reinterpret_cast<const float4*>(&Ws[buf][kk][64 + tx * 4]);
            ull b[4];
            PACK2(b[0], bv0.x, bv0.y);
            PACK2(b[1], bv0.z, bv0.w);
            PACK2(b[2], bv1.x, bv1.y);
            PACK2(b[3], bv1.z, bv1.w);
            const float a[8] = {av0.x, av0.y, av0.z, av0.w, av1.x, av1.y, av1.z, av1.w};
#pragma unroll
            for (int i = 0; i < 8; i++) {
                ull ap;
                PACK2(ap, a[i], a[i]);
                FFMA2(acc[i][0], ap, b[0]);
                FFMA2(acc[i][1], ap, b[1]);
                FFMA2(acc[i][2], ap, b[2]);
                FFMA2(acc[i][3], ap, b[3]);
            }
        }

        if (kb < NSTAGE - 1) {
            const int nbuf = buf ^ 1;
            Xs[nbuf][lhalf + 0][lrow] = xn.x;
            Xs[nbuf][lhalf + 1][lrow] = xn.y;
            Xs[nbuf][lhalf + 2][lrow] = xn.z;
            Xs[nbuf][lhalf + 3][lrow] = xn.w;
            *reinterpret_cast<float4*>(&Ws[nbuf][wr][wf]) = wn;
            __syncthreads();
        }
    }

#pragma unroll
    for (int i = 0; i < 8; i++) {
        const int rloc = (i < 4) ? (ty * 4 + i) : (64 + ty * 4 + (i - 4));
        const int row  = mb * GBM + rloc;
        if (row < N_NODES) {
            float o[8];
            UNPACK2(o[0], o[1], acc[i][0]);
            UNPACK2(o[2], o[3], acc[i][1]);
            UNPACK2(o[4], o[5], acc[i][2]);
            UNPACK2(o[6], o[7], acc[i][3]);
            float* op = out + (size_t)row * FILTERS;
            asm volatile("red.global.add.v4.f32 [%0], {%1, %2, %3, %4};"
                         :: "l"(op + tx * 4), "f"(o[0]), "f"(o[1]), "f"(o[2]), "f"(o[3])
                         : "memory");
            asm volatile("red.global.add.v4.f32 [%0], {%1, %2, %3, %4};"
                         :: "l"(op + 64 + tx * 4), "f"(o[4]), "f"(o[5]), "f"(o[6]), "f"(o[7])
                         : "memory");
        }
    }
}

// ---------------------------------------------------------------------------
extern "C" void kernel_launch(void* const* d_in, const int* in_sizes, int n_in,
                              void* d_out, int out_size) {
    const float* X    = (const float*)d_in[0];   // node_features (20000,128)
    const float* ef   = (const float*)d_in[1];   // edge_features (8,640000)
    const float* Wall = (const float*)d_in[2];   // kernel (8,128,128)
    const float* bias = (const float*)d_in[3];   // bias (128,)
    const int*   idx  = (const int*)d_in[4];     // indices (640000,2) int32
    float*       out  = (float*)d_out;           // (20000,128)

    zero_hist<<<(N_NODES + 255) / 256, 256>>>();
    hist_rows<<<N_EDGES / 256, 256>>>(idx);
    scan_hist<<<1, 1024>>>();
    scatter_sort<<<N_EDGES / 256, 256>>>(idx, ef);

    row_gather<<<(N_NODES + 7) / 8, 256>>>(X);

    init_out<<<(N_NODES * FILTERS) / 256, 256>>>(out, bias);

    dim3 ggrid((N_NODES + GBM - 1) / GBM, K_FOLDS);
    gemm_out<<<ggrid, 256>>>(Wall, out);
}

// round 8
// speedup vs baseline: 1.7437x; 1.1022x over previous
#include <cuda_runtime.h>
#include <cuda_bf16.h>
#include <cstdint>

#define N_NODES 20000
#define N_EDGES 640000
#define C_IN    128
#define K_FOLDS 8
#define FILTERS 128
#define KTOT    (K_FOLDS * C_IN)   // 1024

typedef unsigned long long ull;

// Scratch
__device__ __nv_bfloat16 g_Yh[(size_t)N_NODES * KTOT];   // 41 MB
__device__ __nv_bfloat16 g_Yl[(size_t)N_NODES * KTOT];   // 41 MB
__device__ __nv_bfloat16 g_Wth[FILTERS * KTOT];          // Wt hi: [f][k*128+c]
__device__ __nv_bfloat16 g_Wtl[FILTERS * KTOT];          // Wt lo
__device__ int   g_hist[N_NODES];
__device__ int   g_start[N_NODES + 1];
__device__ int   g_cur[N_NODES];
__device__ int   g_scol[N_EDGES];
__device__ float g_w8[(size_t)N_EDGES * K_FOLDS];

#define PACK2(d, x, y)   asm("mov.b64 %0, {%1,%2};" : "=l"(d) : "f"(x), "f"(y))
#define UNPACK2(x, y, d) asm("mov.b64 {%0,%1}, %2;" : "=f"(x), "=f"(y) : "l"(d))
#define FFMA2(acc, a, b) asm("fma.rn.f32x2 %0, %1, %2, %0;" : "+l"(acc) : "l"(a), "l"(b))

#define SW128(o) ((o) ^ (((o) >> 3) & 0x70))

static __device__ __forceinline__ uint32_t smem_u32(const void* p) {
    uint32_t a;
    asm("{ .reg .u64 t; cvta.to.shared.u64 t, %1; cvt.u32.u64 %0, t; }" : "=r"(a) : "l"(p));
    return a;
}

// ---------------------------------------------------------------------------
// Counting sort by ROW
// ---------------------------------------------------------------------------
__global__ __launch_bounds__(256) void zero_hist() {
    const int i = blockIdx.x * 256 + threadIdx.x;
    if (i < N_NODES) g_hist[i] = 0;
}

__global__ __launch_bounds__(256) void hist_rows(const int* __restrict__ idx) {
    const int e = blockIdx.x * 256 + threadIdx.x;
    const int row = reinterpret_cast<const int2*>(idx)[e].x;
    atomicAdd(&g_hist[row], 1);
}

#define BINS_PER_THREAD 20
__global__ __launch_bounds__(1024) void scan_hist() {
    const int tid  = threadIdx.x;
    const int lane = tid & 31;
    const int wid  = tid >> 5;
    const int base = tid * BINS_PER_THREAD;

    int local[BINS_PER_THREAD];
    int sum = 0;
#pragma unroll
    for (int i = 0; i < BINS_PER_THREAD; i++) {
        const int b = base + i;
        const int v = (b < N_NODES) ? g_hist[b] : 0;
        local[i] = v;
        sum += v;
    }
    int x = sum;
#pragma unroll
    for (int off = 1; off < 32; off <<= 1) {
        int t = __shfl_up_sync(0xffffffffu, x, off);
        if (lane >= off) x += t;
    }
    __shared__ int wsum[32];
    if (lane == 31) wsum[wid] = x;
    __syncthreads();
    if (wid == 0) {
        int w = wsum[lane];
#pragma unroll
        for (int off = 1; off < 32; off <<= 1) {
            int t = __shfl_up_sync(0xffffffffu, w, off);
            if (lane >= off) w += t;
        }
        wsum[lane] = w;
    }
    __syncthreads();
    int run = x - sum + (wid > 0 ? wsum[wid - 1] : 0);
#pragma unroll
    for (int i = 0; i < BINS_PER_THREAD; i++) {
        const int b = base + i;
        if (b < N_NODES) {
            g_start[b] = run;
            g_cur[b]   = run;
            run += local[i];
        }
    }
    if (tid == 1023) g_start[N_NODES] = N_EDGES;
}

__global__ __launch_bounds__(256) void scatter_sort(const int* __restrict__ idx,
                                                    const float* __restrict__ ef) {
    const int e = blockIdx.x * 256 + threadIdx.x;
    const int2 rc = reinterpret_cast<const int2*>(idx)[e];
    const int pos = atomicAdd(&g_cur[rc.x], 1);
    g_scol[pos] = rc.y;
    float w[K_FOLDS];
#pragma unroll
    for (int k = 0; k < K_FOLDS; k++) w[k] = ef[(size_t)k * N_EDGES + e];
    float4* wp = reinterpret_cast<float4*>(g_w8 + (size_t)pos * K_FOLDS);
    wp[0] = make_float4(w[0], w[1], w[2], w[3]);
    wp[1] = make_float4(w[4], w[5], w[6], w[7]);
}

// ---------------------------------------------------------------------------
// prep_w: Wt_hi/lo[f][k*128+c] = bf16 split of Wall[k][c][f]
// ---------------------------------------------------------------------------
__global__ __launch_bounds__(256) void prep_w(const float* __restrict__ Wall) {
    const int i = blockIdx.x * 256 + threadIdx.x;
    if (i >= K_FOLDS * C_IN * FILTERS) return;
    const int f = i & 127;
    const int c = (i >> 7) & 127;
    const int k = i >> 14;
    const float v = Wall[i];
    const __nv_bfloat16 h = __float2bfloat16(v);
    const __nv_bfloat16 l = __float2bfloat16(v - __bfloat162float(h));
    const int o = f * KTOT + k * C_IN + c;
    g_Wth[o] = h;
    g_Wtl[o] = l;
}

// ---------------------------------------------------------------------------
// row_gather: one warp per row; writes bf16 hi/lo split of Y.
// ---------------------------------------------------------------------------
__global__ __launch_bounds__(256) void row_gather(const float* __restrict__ X) {
    const int r    = blockIdx.x * 8 + (threadIdx.x >> 5);
    const int lane = threadIdx.x & 31;
    if (r >= N_NODES) return;

    const int beg = g_start[r];
    const int end = g_start[r + 1];

    ull acc[K_FOLDS][2];
#pragma unroll
    for (int k = 0; k < K_FOLDS; k++) { acc[k][0] = 0ull; acc[k][1] = 0ull; }

    int e = beg;
    for (; e + 1 < end; e += 2) {
        const int c0 = g_scol[e];
        const int c1 = g_scol[e + 1];
        const float4 xv0 = reinterpret_cast<const float4*>(X + (size_t)c0 * C_IN)[lane];
        const float4 xv1 = reinterpret_cast<const float4*>(X + (size_t)c1 * C_IN)[lane];
        const float4* wp = reinterpret_cast<const float4*>(g_w8 + (size_t)e * K_FOLDS);
        const float4 wa0 = wp[0], wa1 = wp[1], wb0 = wp[2], wb1 = wp[3];
        const float wa[K_FOLDS] = {wa0.x, wa0.y, wa0.z, wa0.w, wa1.x, wa1.y, wa1.z, wa1.w};
        const float wb[K_FOLDS] = {wb0.x, wb0.y, wb0.z, wb0.w, wb1.x, wb1.y, wb1.z, wb1.w};
        ull x0lo, x0hi, x1lo, x1hi;
        PACK2(x0lo, xv0.x, xv0.y); PACK2(x0hi, xv0.z, xv0.w);
        PACK2(x1lo, xv1.x, xv1.y); PACK2(x1hi, xv1.z, xv1.w);
#pragma unroll
        for (int k = 0; k < K_FOLDS; k++) {
            ull wk0, wk1;
            PACK2(wk0, wa[k], wa[k]);
            PACK2(wk1, wb[k], wb[k]);
            FFMA2(acc[k][0], wk0, x0lo);
            FFMA2(acc[k][1], wk0, x0hi);
            FFMA2(acc[k][0], wk1, x1lo);
            FFMA2(acc[k][1], wk1, x1hi);
        }
    }
    if (e < end) {
        const int c0 = g_scol[e];
        const float4 xv0 = reinterpret_cast<const float4*>(X + (size_t)c0 * C_IN)[lane];
        const float4* wp = reinterpret_cast<const float4*>(g_w8 + (size_t)e * K_FOLDS);
        const float4 wa0 = wp[0], wa1 = wp[1];
        const float wa[K_FOLDS] = {wa0.x, wa0.y, wa0.z, wa0.w, wa1.x, wa1.y, wa1.z, wa1.w};
        ull x0lo, x0hi;
        PACK2(x0lo, xv0.x, xv0.y); PACK2(x0hi, xv0.z, xv0.w);
#pragma unroll
        for (int k = 0; k < K_FOLDS; k++) {
            ull wk0;
            PACK2(wk0, wa[k], wa[k]);
            FFMA2(acc[k][0], wk0, x0lo);
            FFMA2(acc[k][1], wk0, x0hi);
        }
    }

    __nv_bfloat162* yh = reinterpret_cast<__nv_bfloat162*>(g_Yh + (size_t)r * KTOT);
    __nv_bfloat162* yl = reinterpret_cast<__nv_bfloat162*>(g_Yl + (size_t)r * KTOT);
#pragma unroll
    for (int k = 0; k < K_FOLDS; k++) {
        float v[4];
        UNPACK2(v[0], v[1], acc[k][0]);
        UNPACK2(v[2], v[3], acc[k][1]);
        __nv_bfloat16 h[4], l[4];
#pragma unroll
        for (int j = 0; j < 4; j++) {
            h[j] = __float2bfloat16(v[j]);
            l[j] = __float2bfloat16(v[j] - __bfloat162float(h[j]));
        }
        const int o = k * (C_IN / 2) + lane * 2;
        yh[o]     = __halves2bfloat162(h[0], h[1]);
        yh[o + 1] = __halves2bfloat162(h[2], h[3]);
        yl[o]     = __halves2bfloat162(l[0], l[1]);
        yl[o + 1] = __halves2bfloat162(l[2], l[3]);
    }
}

// ---------------------------------------------------------------------------
// gemm_mma: out = Yh@Wth + Yh@Wtl + Yl@Wth + bias   (mma.sync bf16, fp32 acc)
// CTA: 64 M-rows x 128 N. 8 warps (2M x 4N), warp tile 32x32.
// K=1024 in 16 stages of 64; cp.async double buffer; SW128 + ldmatrix.
// ---------------------------------------------------------------------------
#define STG_BYTES 49152
#define SM_AH 0
#define SM_AL 8192
#define SM_BH 16384
#define SM_BL 32768
#define GEMM_SMEM (2 * STG_BYTES)

#define CPA(dst, src) asm volatile("cp.async.cg.shared.global [%0], [%1], 16;" \
                                   :: "r"(dst), "l"(src) : "memory")
#define CPC()  asm volatile("cp.async.commit_group;" ::: "memory")
#define CPW1() asm volatile("cp.async.wait_group 1;" ::: "memory")
#define CPW0() asm volatile("cp.async.wait_group 0;" ::: "memory")

#define LDSM4(r, addr)                                                            \
    asm volatile("ldmatrix.sync.aligned.m8n8.x4.shared.b16 {%0,%1,%2,%3}, [%4];"  \
        : "=r"((r)[0]), "=r"((r)[1]), "=r"((r)[2]), "=r"((r)[3]) : "r"(addr))

#define MMA_BF16(c, a, b0, b1)                                                    \
    asm volatile("mma.sync.aligned.m16n8k16.row.col.f32.bf16.bf16.f32 "           \
        "{%0,%1,%2,%3}, {%4,%5,%6,%7}, {%8,%9}, {%0,%1,%2,%3};"                   \
        : "+f"((c)[0]), "+f"((c)[1]), "+f"((c)[2]), "+f"((c)[3])                  \
        : "r"((a)[0]), "r"((a)[1]), "r"((a)[2]), "r"((a)[3]), "r"(b0), "r"(b1))

__global__ __launch_bounds__(256, 2) void gemm_mma(const float* __restrict__ bias,
                                                   float* __restrict__ out) {
    extern __shared__ char dynsm[];
    __shared__ float s_bias[FILTERS];

    const int tid  = threadIdx.x;
    const int lane = tid & 31;
    const int wid  = tid >> 5;
    const int mb   = blockIdx.x;

    if (tid < FILTERS) s_bias[tid] = bias[tid];

    const int wm = wid >> 2;   // 0..1  (32-row group)
    const int wn = wid & 3;    // 0..3  (32-col group)

    const uint32_t smbase = smem_u32(dynsm);

    // loader mapping
    const int ra = tid >> 2;                 // 0..63 A row
    const int ca = (tid & 3) * 32;           // A byte col base (2 chunks of 16)
    const int rb = tid >> 1;                 // 0..127 B row
    const int cbb = (tid & 1) * 64;          // B byte col base (4 chunks of 16)
    const int ga_row = min(mb * 64 + ra, N_NODES - 1);
    const char* gYh = reinterpret_cast<const char*>(g_Yh + (size_t)ga_row * KTOT);
    const char* gYl = reinterpret_cast<const char*>(g_Yl + (size_t)ga_row * KTOT);
    const char* gWh = reinterpret_cast<const char*>(g_Wth + (size_t)rb * KTOT);
    const char* gWl = reinterpret_cast<const char*>(g_Wtl + (size_t)rb * KTOT);
    const uint32_t saoff0 = SW128((uint32_t)(ra * 128 + ca));
    const uint32_t saoff1 = SW128((uint32_t)(ra * 128 + ca + 16));
    uint32_t sboff[4];
#pragma unroll
    for (int i = 0; i < 4; i++) sboff[i] = SW128((uint32_t)(rb * 128 + cbb + i * 16));

    // per-lane ldmatrix offsets
    const int trow = lane & 7;
    const int bit3 = (lane >> 3) & 1;
    const int bit4 = (lane >> 4) & 1;
    const int am60 = (trow << 4) & 0x60;
    const int am10 = (trow << 4) & 0x10;
    const int arow = trow + bit3 * 8;
    const int acol0 = (bit4 * 16) ^ am10;
    const int brow = trow + bit4 * 8;
    const int bcol0 = (bit3 * 16) ^ am10;

    uint32_t aoff[2], boff[2];
#pragma unroll
    for (int mi = 0; mi < 2; mi++)
        aoff[mi] = (uint32_t)((wm * 32 + mi * 16 + arow) * 128 + acol0);
#pragma unroll
    for (int nj = 0; nj < 2; nj++)
        boff[nj] = (uint32_t)((wn * 32 + nj * 16 + brow) * 128 + bcol0);

    float acc[2][4][4];
#pragma unroll
    for (int mi = 0; mi < 2; mi++)
#pragma unroll
        for (int ni = 0; ni < 4; ni++)
#pragma unroll
            for (int j = 0; j < 4; j++) acc[mi][ni][j] = 0.0f;

    // ---- stage 0 issue ----
    {
        const uint32_t sb = smbase;
        CPA(sb + SM_AH + saoff0, gYh + ca);
        CPA(sb + SM_AH + saoff1, gYh + ca + 16);
        CPA(sb + SM_AL + saoff0, gYl + ca);
        CPA(sb + SM_AL + saoff1, gYl + ca + 16);
#pragma unroll
        for (int i = 0; i < 4; i++) {
            CPA(sb + SM_BH + sboff[i], gWh + cbb + i * 16);
            CPA(sb + SM_BL + sboff[i], gWl + cbb + i * 16);
        }
        CPC();
    }

    for (int s = 0; s < 16; ++s) {
        if (s < 15) {
            const uint32_t sb = smbase + (uint32_t)(((s + 1) & 1) * STG_BYTES);
            const int kb = (s + 1) * 128;
            CPA(sb + SM_AH + saoff0, gYh + kb + ca);
            CPA(sb + SM_AH + saoff1, gYh + kb + ca + 16);
            CPA(sb + SM_AL + saoff0, gYl + kb + ca);
            CPA(sb + SM_AL + saoff1, gYl + kb + ca + 16);
#pragma unroll
            for (int i = 0; i < 4; i++) {
                CPA(sb + SM_BH + sboff[i], gWh + kb + cbb + i * 16);
                CPA(sb + SM_BL + sboff[i], gWl + kb + cbb + i * 16);
            }
            CPC();
            CPW1();
        } else {
            CPW0();
        }
        __syncthreads();

        const uint32_t cb = smbase + (uint32_t)((s & 1) * STG_BYTES);
        const uint32_t sAh = cb + SM_AH, sAl = cb + SM_AL;
        const uint32_t sBh = cb + SM_BH, sBl = cb + SM_BL;

#pragma unroll
        for (int ks = 0; ks < 4; ++ks) {
            const uint32_t kx = (uint32_t)((ks * 32) ^ am60);
            uint32_t ah[2][4], al[2][4], bh[2][4], bl[2][4];
            LDSM4(ah[0], sAh + aoff[0] + kx);
            LDSM4(ah[1], sAh + aoff[1] + kx);
            LDSM4(al[0], sAl + aoff[0] + kx);
            LDSM4(al[1], sAl + aoff[1] + kx);
            LDSM4(bh[0], sBh + boff[0] + kx);
            LDSM4(bh[1], sBh + boff[1] + kx);
            LDSM4(bl[0], sBl + boff[0] + kx);
            LDSM4(bl[1], sBl + boff[1] + kx);
#pragma unroll
            for (int ni = 0; ni < 4; ++ni) {
                const uint32_t b0h = bh[ni >> 1][(ni & 1) * 2];
                const uint32_t b1h = bh[ni >> 1][(ni & 1) * 2 + 1];
                const uint32_t b0l = bl[ni >> 1][(ni & 1) * 2];
                const uint32_t b1l = bl[ni >> 1][(ni & 1) * 2 + 1];
                MMA_BF16(acc[0][ni], ah[0], b0h, b1h);
                MMA_BF16(acc[1][ni], ah[1], b0h, b1h);
                MMA_BF16(acc[0][ni], ah[0], b0l, b1l);
                MMA_BF16(acc[1][ni], ah[1], b0l, b1l);
                MMA_BF16(acc[0][ni], al[0], b0h, b1h);
                MMA_BF16(acc[1][ni], al[1], b0h, b1h);
            }
        }
        __syncthreads();
    }

    // epilogue
    const int g   = lane >> 2;
    const int tig = lane & 3;
#pragma unroll
    for (int mi = 0; mi < 2; ++mi) {
        const int r0 = mb * 64 + wm * 32 + mi * 16 + g;
#pragma unroll
        for (int ni = 0; ni < 4; ++ni) {
            const int c0 = wn * 32 + ni * 8 + tig * 2;
            const float2 bb = *reinterpret_cast<const float2*>(&s_bias[c0]);
            if (r0 < N_NODES) {
                float2 v = make_float2(acc[mi][ni][0] + bb.x, acc[mi][ni][1] + bb.y);
                *reinterpret_cast<float2*>(out + (size_t)r0 * FILTERS + c0) = v;
            }
            if (r0 + 8 < N_NODES) {
                float2 v = make_float2(acc[mi][ni][2] + bb.x, acc[mi][ni][3] + bb.y);
                *reinterpret_cast<float2*>(out + (size_t)(r0 + 8) * FILTERS + c0) = v;
            }
        }
    }
}

// ---------------------------------------------------------------------------
extern "C" void kernel_launch(void* const* d_in, const int* in_sizes, int n_in,
                              void* d_out, int out_size) {
    const float* X    = (const float*)d_in[0];   // node_features (20000,128)
    const float* ef   = (const float*)d_in[1];   // edge_features (8,640000)
    const float* Wall = (const float*)d_in[2];   // kernel (8,128,128)
    const float* bias = (const float*)d_in[3];   // bias (128,)
    const int*   idx  = (const int*)d_in[4];     // indices (640000,2) int32
    float*       out  = (float*)d_out;           // (20000,128)

    cudaFuncSetAttribute(gemm_mma, cudaFuncAttributeMaxDynamicSharedMemorySize, GEMM_SMEM);

    prep_w<<<(K_FOLDS * C_IN * FILTERS + 255) / 256, 256>>>(Wall);

    zero_hist<<<(N_NODES + 255) / 256, 256>>>();
    hist_rows<<<N_EDGES / 256, 256>>>(idx);
    scan_hist<<<1, 1024>>>();
    scatter_sort<<<N_EDGES / 256, 256>>>(idx, ef);

    row_gather<<<(N_NODES + 7) / 8, 256>>>(X);

    gemm_mma<<<(N_NODES + 63) / 64, 256, GEMM_SMEM>>>(bias, out);
}

// round 9
// speedup vs baseline: 2.0098x; 1.1526x over previous
#include <cuda_runtime.h>
#include <cuda_bf16.h>
#include <cstdint>

#define N_NODES 20000
#define N_EDGES 640000
#define C_IN    128
#define K_FOLDS 8
#define FILTERS 128
#define KTOT    (K_FOLDS * C_IN)   // 1024

typedef unsigned long long ull;

// Scratch
__device__ __nv_bfloat16 g_Yh[(size_t)N_NODES * KTOT];   // 41 MB
__device__ __nv_bfloat16 g_Yl[(size_t)N_NODES * KTOT];   // 41 MB
__device__ __nv_bfloat16 g_Wth[FILTERS * KTOT];          // Wt hi: [f][k*128+c]
__device__ __nv_bfloat16 g_Wtl[FILTERS * KTOT];          // Wt lo
__device__ int   g_hist[N_NODES];
__device__ int   g_start[N_NODES + 1];
__device__ int   g_cur[N_NODES];
__device__ int   g_scol[N_EDGES];
__device__ float g_w8[(size_t)N_EDGES * K_FOLDS];

#define PACK2(d, x, y)   asm("mov.b64 %0, {%1,%2};" : "=l"(d) : "f"(x), "f"(y))
#define UNPACK2(x, y, d) asm("mov.b64 {%0,%1}, %2;" : "=f"(x), "=f"(y) : "l"(d))
#define FFMA2(acc, a, b) asm("fma.rn.f32x2 %0, %1, %2, %0;" : "+l"(acc) : "l"(a), "l"(b))

#define SW128(o) ((o) ^ (((o) >> 3) & 0x70))

static __device__ __forceinline__ uint32_t smem_u32(const void* p) {
    uint32_t a;
    asm("{ .reg .u64 t; cvta.to.shared.u64 t, %1; cvt.u32.u64 %0, t; }" : "=r"(a) : "l"(p));
    return a;
}

// ---------------------------------------------------------------------------
// prep_w + zero_hist fused:
//  Wt_hi/lo[f][k*128+c] = bf16 split of Wall[k][c][f]; first 20000 zero g_hist.
// ---------------------------------------------------------------------------
__global__ __launch_bounds__(256) void prep_w(const float* __restrict__ Wall) {
    const int i = blockIdx.x * 256 + threadIdx.x;
    if (i < N_NODES) g_hist[i] = 0;
    if (i >= K_FOLDS * C_IN * FILTERS) return;
    const int f = i & 127;
    const int c = (i >> 7) & 127;
    const int k = i >> 14;
    const float v = Wall[i];
    const __nv_bfloat16 h = __float2bfloat16(v);
    const __nv_bfloat16 l = __float2bfloat16(v - __bfloat162float(h));
    const int o = f * KTOT + k * C_IN + c;
    g_Wth[o] = h;
    g_Wtl[o] = l;
}

__global__ __launch_bounds__(256) void hist_rows(const int* __restrict__ idx) {
    const int e = blockIdx.x * 256 + threadIdx.x;
    const int row = reinterpret_cast<const int2*>(idx)[e].x;
    atomicAdd(&g_hist[row], 1);
}

// ---------------------------------------------------------------------------
// scan_hist v3: smem-staged. Coalesced int4 load of all bins -> smem,
// per-thread local scan in smem, shfl block scan, coalesced int4 store.
// ---------------------------------------------------------------------------
#define BINS_PER_THREAD 20   // 1024*20 >= 20000
#define SCAN_SMEM (N_NODES * 4)

__global__ __launch_bounds__(1024) void scan_hist() {
    extern __shared__ int s[];
    const int tid  = threadIdx.x;
    const int lane = tid & 31;
    const int wid  = tid >> 5;

    // coalesced load (20000 = 5000 int4)
    int4* s4 = reinterpret_cast<int4*>(s);
    const int4* g4 = reinterpret_cast<const int4*>(g_hist);
    for (int i = tid; i < N_NODES / 4; i += 1024) s4[i] = g4[i];
    __syncthreads();

    const int base = tid * BINS_PER_THREAD;
    int local[BINS_PER_THREAD];
    int sum = 0;
#pragma unroll
    for (int i = 0; i < BINS_PER_THREAD; i++) {
        const int b = base + i;
        const int v = (b < N_NODES) ? s[b] : 0;
        local[i] = v;
        sum += v;
    }
    int x = sum;
#pragma unroll
    for (int off = 1; off < 32; off <<= 1) {
        int t = __shfl_up_sync(0xffffffffu, x, off);
        if (lane >= off) x += t;
    }
    __shared__ int wsum[32];
    if (lane == 31) wsum[wid] = x;
    __syncthreads();
    if (wid == 0) {
        int w = wsum[lane];
#pragma unroll
        for (int off = 1; off < 32; off <<= 1) {
            int t = __shfl_up_sync(0xffffffffu, w, off);
            if (lane >= off) w += t;
        }
        wsum[lane] = w;
    }
    __syncthreads();
    int run = x - sum + (wid > 0 ? wsum[wid - 1] : 0);
#pragma unroll
    for (int i = 0; i < BINS_PER_THREAD; i++) {
        const int b = base + i;
        if (b < N_NODES) {
            s[b] = run;
            run += local[i];
        }
    }
    __syncthreads();

    // coalesced store
    int4* st4 = reinterpret_cast<int4*>(g_start);
    int4* cu4 = reinterpret_cast<int4*>(g_cur);
    for (int i = tid; i < N_NODES / 4; i += 1024) {
        const int4 v = s4[i];
        st4[i] = v;
        cu4[i] = v;
    }
    if (tid == 0) g_start[N_NODES] = N_EDGES;
}

__global__ __launch_bounds__(256) void scatter_sort(const int* __restrict__ idx,
                                                    const float* __restrict__ ef) {
    const int e = blockIdx.x * 256 + threadIdx.x;
    const int2 rc = reinterpret_cast<const int2*>(idx)[e];
    const int pos = atomicAdd(&g_cur[rc.x], 1);
    g_scol[pos] = rc.y;
    float w[K_FOLDS];
#pragma unroll
    for (int k = 0; k < K_FOLDS; k++) w[k] = ef[(size_t)k * N_EDGES + e];
    float4* wp = reinterpret_cast<float4*>(g_w8 + (size_t)pos * K_FOLDS);
    wp[0] = make_float4(w[0], w[1], w[2], w[3]);
    wp[1] = make_float4(w[4], w[5], w[6], w[7]);
}

// ---------------------------------------------------------------------------
// row_gather: one warp per row; unroll x4; writes bf16 hi/lo split of Y.
// ---------------------------------------------------------------------------
__global__ __launch_bounds__(256) void row_gather(const float* __restrict__ X) {
    const int r    = blockIdx.x * 8 + (threadIdx.x >> 5);
    const int lane = threadIdx.x & 31;
    if (r >= N_NODES) return;

    const int beg = g_start[r];
    const int end = g_start[r + 1];

    ull acc[K_FOLDS][2];
#pragma unroll
    for (int k = 0; k < K_FOLDS; k++) { acc[k][0] = 0ull; acc[k][1] = 0ull; }

    int e = beg;
    for (; e + 3 < end; e += 4) {
        int   cc[4];
        float4 xv[4];
#pragma unroll
        for (int j = 0; j < 4; j++) cc[j] = g_scol[e + j];
#pragma unroll
        for (int j = 0; j < 4; j++)
            xv[j] = reinterpret_cast<const float4*>(X + (size_t)cc[j] * C_IN)[lane];
        const float4* wp = reinterpret_cast<const float4*>(g_w8 + (size_t)e * K_FOLDS);
        float4 wv[8];
#pragma unroll
        for (int j = 0; j < 8; j++) wv[j] = wp[j];

        ull xlo[4], xhi[4];
#pragma unroll
        for (int j = 0; j < 4; j++) {
            PACK2(xlo[j], xv[j].x, xv[j].y);
            PACK2(xhi[j], xv[j].z, xv[j].w);
        }
        const float* wf = reinterpret_cast<const float*>(wv);
#pragma unroll
        for (int k = 0; k < K_FOLDS; k++) {
#pragma unroll
            for (int j = 0; j < 4; j++) {
                const float w = wf[j * 8 + k];
                ull wk;
                PACK2(wk, w, w);
                FFMA2(acc[k][0], wk, xlo[j]);
                FFMA2(acc[k][1], wk, xhi[j]);
            }
        }
    }
    for (; e < end; ++e) {
        const int c0 = g_scol[e];
        const float4 xv0 = reinterpret_cast<const float4*>(X + (size_t)c0 * C_IN)[lane];
        const float4* wp = reinterpret_cast<const float4*>(g_w8 + (size_t)e * K_FOLDS);
        const float4 wa0 = wp[0], wa1 = wp[1];
        const float wa[K_FOLDS] = {wa0.x, wa0.y, wa0.z, wa0.w, wa1.x, wa1.y, wa1.z, wa1.w};
        ull x0lo, x0hi;
        PACK2(x0lo, xv0.x, xv0.y); PACK2(x0hi, xv0.z, xv0.w);
#pragma unroll
        for (int k = 0; k < K_FOLDS; k++) {
            ull wk0;
            PACK2(wk0, wa[k], wa[k]);
            FFMA2(acc[k][0], wk0, x0lo);
            FFMA2(acc[k][1], wk0, x0hi);
        }
    }

    __nv_bfloat162* yh = reinterpret_cast<__nv_bfloat162*>(g_Yh + (size_t)r * KTOT);
    __nv_bfloat162* yl = reinterpret_cast<__nv_bfloat162*>(g_Yl + (size_t)r * KTOT);
#pragma unroll
    for (int k = 0; k < K_FOLDS; k++) {
        float v[4];
        UNPACK2(v[0], v[1], acc[k][0]);
        UNPACK2(v[2], v[3], acc[k][1]);
        __nv_bfloat16 h[4], l[4];
#pragma unroll
        for (int j = 0; j < 4; j++) {
            h[j] = __float2bfloat16(v[j]);
            l[j] = __float2bfloat16(v[j] - __bfloat162float(h[j]));
        }
        const int o = k * (C_IN / 2) + lane * 2;
        yh[o]     = __halves2bfloat162(h[0], h[1]);
        yh[o + 1] = __halves2bfloat162(h[2], h[3]);
        yl[o]     = __halves2bfloat162(l[0], l[1]);
        yl[o + 1] = __halves2bfloat162(l[2], l[3]);
    }
}

// ---------------------------------------------------------------------------
// gemm_mma: out = Yh@Wth + Yh@Wtl + Yl@Wth + bias   (mma.sync bf16, fp32 acc)
// CTA: 64 M-rows x 128 N. 8 warps (2M x 4N), warp tile 32x32.
// K=1024 in 16 stages of 64; cp.async double buffer; SW128 + ldmatrix.
// ---------------------------------------------------------------------------
#define STG_BYTES 49152
#define SM_AH 0
#define SM_AL 8192
#define SM_BH 16384
#define SM_BL 32768
#define GEMM_SMEM (2 * STG_BYTES)

#define CPA(dst, src) asm volatile("cp.async.cg.shared.global [%0], [%1], 16;" \
                                   :: "r"(dst), "l"(src) : "memory")
#define CPC()  asm volatile("cp.async.commit_group;" ::: "memory")
#define CPW1() asm volatile("cp.async.wait_group 1;" ::: "memory")
#define CPW0() asm volatile("cp.async.wait_group 0;" ::: "memory")

#define LDSM4(r, addr)                                                            \
    asm volatile("ldmatrix.sync.aligned.m8n8.x4.shared.b16 {%0,%1,%2,%3}, [%4];"  \
        : "=r"((r)[0]), "=r"((r)[1]), "=r"((r)[2]), "=r"((r)[3]) : "r"(addr))

#define MMA_BF16(c, a, b0, b1)                                                    \
    asm volatile("mma.sync.aligned.m16n8k16.row.col.f32.bf16.bf16.f32 "           \
        "{%0,%1,%2,%3}, {%4,%5,%6,%7}, {%8,%9}, {%0,%1,%2,%3};"                   \
        : "+f"((c)[0]), "+f"((c)[1]), "+f"((c)[2]), "+f"((c)[3])                  \
        : "r"((a)[0]), "r"((a)[1]), "r"((a)[2]), "r"((a)[3]), "r"(b0), "r"(b1))

__global__ __launch_bounds__(256, 2) void gemm_mma(const float* __restrict__ bias,
                                                   float* __restrict__ out) {
    extern __shared__ char dynsm[];
    __shared__ float s_bias[FILTERS];

    const int tid  = threadIdx.x;
    const int lane = tid & 31;
    const int wid  = tid >> 5;
    const int mb   = blockIdx.x;

    if (tid < FILTERS) s_bias[tid] = bias[tid];

    const int wm = wid >> 2;   // 0..1  (32-row group)
    const int wn = wid & 3;    // 0..3  (32-col group)

    const uint32_t smbase = smem_u32(dynsm);

    // loader mapping
    const int ra = tid >> 2;                 // 0..63 A row
    const int ca = (tid & 3) * 32;           // A byte col base (2 chunks of 16)
    const int rb = tid >> 1;                 // 0..127 B row
    const int cbb = (tid & 1) * 64;          // B byte col base (4 chunks of 16)
    const int ga_row = min(mb * 64 + ra, N_NODES - 1);
    const char* gYh = reinterpret_cast<const char*>(g_Yh + (size_t)ga_row * KTOT);
    const char* gYl = reinterpret_cast<const char*>(g_Yl + (size_t)ga_row * KTOT);
    const char* gWh = reinterpret_cast<const char*>(g_Wth + (size_t)rb * KTOT);
    const char* gWl = reinterpret_cast<const char*>(g_Wtl + (size_t)rb * KTOT);
    const uint32_t saoff0 = SW128((uint32_t)(ra * 128 + ca));
    const uint32_t saoff1 = SW128((uint32_t)(ra * 128 + ca + 16));
    uint32_t sboff[4];
#pragma unroll
    for (int i = 0; i < 4; i++) sboff[i] = SW128((uint32_t)(rb * 128 + cbb + i * 16));

    // per-lane ldmatrix offsets
    const int trow = lane & 7;
    const int bit3 = (lane >> 3) & 1;
    const int bit4 = (lane >> 4) & 1;
    const int am60 = (trow << 4) & 0x60;
    const int am10 = (trow << 4) & 0x10;
    const int arow = trow + bit3 * 8;
    const int acol0 = (bit4 * 16) ^ am10;
    const int brow = trow + bit4 * 8;
    const int bcol0 = (bit3 * 16) ^ am10;

    uint32_t aoff[2], boff[2];
#pragma unroll
    for (int mi = 0; mi < 2; mi++)
        aoff[mi] = (uint32_t)((wm * 32 + mi * 16 + arow) * 128 + acol0);
#pragma unroll
    for (int nj = 0; nj < 2; nj++)
        boff[nj] = (uint32_t)((wn * 32 + nj * 16 + brow) * 128 + bcol0);

    float acc[2][4][4];
#pragma unroll
    for (int mi = 0; mi < 2; mi++)
#pragma unroll
        for (int ni = 0; ni < 4; ni++)
#pragma unroll
            for (int j = 0; j < 4; j++) acc[mi][ni][j] = 0.0f;

    // ---- stage 0 issue ----
    {
        const uint32_t sb = smbase;
        CPA(sb + SM_AH + saoff0, gYh + ca);
        CPA(sb + SM_AH + saoff1, gYh + ca + 16);
        CPA(sb + SM_AL + saoff0, gYl + ca);
        CPA(sb + SM_AL + saoff1, gYl + ca + 16);
#pragma unroll
        for (int i = 0; i < 4; i++) {
            CPA(sb + SM_BH + sboff[i], gWh + cbb + i * 16);
            CPA(sb + SM_BL + sboff[i], gWl + cbb + i * 16);
        }
        CPC();
    }

    for (int s = 0; s < 16; ++s) {
        if (s < 15) {
            const uint32_t sb = smbase + (uint32_t)(((s + 1) & 1) * STG_BYTES);
            const int kb = (s + 1) * 128;
            CPA(sb + SM_AH + saoff0, gYh + kb + ca);
            CPA(sb + SM_AH + saoff1, gYh + kb + ca + 16);
            CPA(sb + SM_AL + saoff0, gYl + kb + ca);
            CPA(sb + SM_AL + saoff1, gYl + kb + ca + 16);
#pragma unroll
            for (int i = 0; i < 4; i++) {
                CPA(sb + SM_BH + sboff[i], gWh + kb + cbb + i * 16);
                CPA(sb + SM_BL + sboff[i], gWl + kb + cbb + i * 16);
            }
            CPC();
            CPW1();
        } else {
            CPW0();
        }
        __syncthreads();

        const uint32_t cb = smbase + (uint32_t)((s & 1) * STG_BYTES);
        const uint32_t sAh = cb + SM_AH, sAl = cb + SM_AL;
        const uint32_t sBh = cb + SM_BH, sBl = cb + SM_BL;

#pragma unroll
        for (int ks = 0; ks < 4; ++ks) {
            const uint32_t kx = (uint32_t)((ks * 32) ^ am60);
            uint32_t ah[2][4], al[2][4], bh[2][4], bl[2][4];
            LDSM4(ah[0], sAh + aoff[0] + kx);
            LDSM4(ah[1], sAh + aoff[1] + kx);
            LDSM4(al[0], sAl + aoff[0] + kx);
            LDSM4(al[1], sAl + aoff[1] + kx);
            LDSM4(bh[0], sBh + boff[0] + kx);
            LDSM4(bh[1], sBh + boff[1] + kx);
            LDSM4(bl[0], sBl + boff[0] + kx);
            LDSM4(bl[1], sBl + boff[1] + kx);
#pragma unroll
            for (int ni = 0; ni < 4; ++ni) {
                const uint32_t b0h = bh[ni >> 1][(ni & 1) * 2];
                const uint32_t b1h = bh[ni >> 1][(ni & 1) * 2 + 1];
                const uint32_t b0l = bl[ni >> 1][(ni & 1) * 2];
                const uint32_t b1l = bl[ni >> 1][(ni & 1) * 2 + 1];
                MMA_BF16(acc[0][ni], ah[0], b0h, b1h);
                MMA_BF16(acc[1][ni], ah[1], b0h, b1h);
                MMA_BF16(acc[0][ni], ah[0], b0l, b1l);
                MMA_BF16(acc[1][ni], ah[1], b0l, b1l);
                MMA_BF16(acc[0][ni], al[0], b0h, b1h);
                MMA_BF16(acc[1][ni], al[1], b0h, b1h);
            }
        }
        __syncthreads();
    }

    // epilogue
    const int g   = lane >> 2;
    const int tig = lane & 3;
#pragma unroll
    for (int mi = 0; mi < 2; ++mi) {
        const int r0 = mb * 64 + wm * 32 + mi * 16 + g;
#pragma unroll
        for (int ni = 0; ni < 4; ++ni) {
            const int c0 = wn * 32 + ni * 8 + tig * 2;
            const float2 bb = *reinterpret_cast<const float2*>(&s_bias[c0]);
            if (r0 < N_NODES) {
                float2 v = make_float2(acc[mi][ni][0] + bb.x, acc[mi][ni][1] + bb.y);
                *reinterpret_cast<float2*>(out + (size_t)r0 * FILTERS + c0) = v;
            }
            if (r0 + 8 < N_NODES) {
                float2 v = make_float2(acc[mi][ni][2] + bb.x, acc[mi][ni][3] + bb.y);
                *reinterpret_cast<float2*>(out + (size_t)(r0 + 8) * FILTERS + c0) = v;
            }
        }
    }
}

// ---------------------------------------------------------------------------
extern "C" void kernel_launch(void* const* d_in, const int* in_sizes, int n_in,
                              void* d_out, int out_size) {
    const float* X    = (const float*)d_in[0];   // node_features (20000,128)
    const float* ef   = (const float*)d_in[1];   // edge_features (8,640000)
    const float* Wall = (const float*)d_in[2];   // kernel (8,128,128)
    const float* bias = (const float*)d_in[3];   // bias (128,)
    const int*   idx  = (const int*)d_in[4];     // indices (640000,2) int32
    float*       out  = (float*)d_out;           // (20000,128)

    cudaFuncSetAttribute(gemm_mma, cudaFuncAttributeMaxDynamicSharedMemorySize, GEMM_SMEM);
    cudaFuncSetAttribute(scan_hist, cudaFuncAttributeMaxDynamicSharedMemorySize, SCAN_SMEM);

    prep_w<<<(K_FOLDS * C_IN * FILTERS + 255) / 256, 256>>>(Wall);

    hist_rows<<<N_EDGES / 256, 256>>>(idx);
    scan_hist<<<1, 1024, SCAN_SMEM>>>();
    scatter_sort<<<N_EDGES / 256, 256>>>(idx, ef);

    row_gather<<<(N_NODES + 7) / 8, 256>>>(X);

    gemm_mma<<<(N_NODES + 63) / 64, 256, GEMM_SMEM>>>(bias, out);
}